// round 6
// baseline (speedup 1.0000x reference)
#include <cuda_runtime.h>
#include <cstring>

#define BB 128
#define TT 512
#define II 128
#define HH 256

__device__ float g_xp[(size_t)BB * TT * HH];   // [B][T][H] fp32 scratch

// Packed fp32x2 FMA (sm_103a): two fp32 FMA lanes per issue.
__device__ __forceinline__ float2 ffma2(float2 a, float2 b, float2 c) {
    unsigned long long ua, ub, uc, ud;
    memcpy(&ua, &a, 8); memcpy(&ub, &b, 8); memcpy(&uc, &c, 8);
    asm("fma.rn.f32x2 %0, %1, %2, %3;" : "=l"(ud) : "l"(ua), "l"(ub), "l"(uc));
    float2 d; memcpy(&d, &ud, 8); return d;
}

// ---------------------------------------------------------------------------
// Phase 1: xp[r,h] = x[r,:] . W_ih[h,:] + (b_ih[h] + b_hh[h])
// 128 CTAs x 256 threads; W_ih row per thread in regs; x double-buffered.
// ---------------------------------------------------------------------------
__global__ void __launch_bounds__(256, 1)
rnn_xproj(const float* __restrict__ x,
          const float* __restrict__ W_ih,
          const float* __restrict__ b_ih,
          const float* __restrict__ b_hh) {
    __shared__ float xs[2][8 * II];

    const int h = threadIdx.x;

    const float4* Wi4 = (const float4*)W_ih;
    float4 wreg[32];
#pragma unroll
    for (int q = 0; q < 32; q++) wreg[q] = Wi4[h * 32 + q];

    const float bias = b_ih[h] + b_hh[h];
    const size_t base_row = (size_t)blockIdx.x * 512;

    ((float4*)xs[0])[h] = ((const float4*)(x + base_row * II))[h];
    __syncthreads();

    for (int tile = 0; tile < 64; tile++) {
        const int cur = tile & 1;
        if (tile < 63) {
            ((float4*)xs[cur ^ 1])[h] =
                ((const float4*)(x + (base_row + (size_t)(tile + 1) * 8) * II))[h];
        }

        const size_t r0 = base_row + (size_t)tile * 8;
#pragma unroll
        for (int r = 0; r < 8; r += 2) {
            const float4* x0 = (const float4*)(xs[cur] + r * II);
            const float4* x1 = (const float4*)(xs[cur] + (r + 1) * II);
            float2 a0 = make_float2(bias, 0.0f), a1 = make_float2(0.0f, 0.0f);
            float2 c0 = make_float2(bias, 0.0f), c1 = make_float2(0.0f, 0.0f);
#pragma unroll
            for (int q = 0; q < 32; q++) {
                float4 xv = x0[q], yv = x1[q];
                float2 wlo = make_float2(wreg[q].x, wreg[q].y);
                float2 whi = make_float2(wreg[q].z, wreg[q].w);
                a0 = ffma2(make_float2(xv.x, xv.y), wlo, a0);
                a1 = ffma2(make_float2(xv.z, xv.w), whi, a1);
                c0 = ffma2(make_float2(yv.x, yv.y), wlo, c0);
                c1 = ffma2(make_float2(yv.z, yv.w), whi, c1);
            }
            g_xp[(r0 + r) * HH + h]     = (a0.x + a0.y) + (a1.x + a1.y);
            g_xp[(r0 + r + 1) * HH + h] = (c0.x + c0.y) + (c1.x + c1.y);
        }
        __syncthreads();
    }
}

// ---------------------------------------------------------------------------
// Phase 2 + 3: recurrent scan, TWO batches per CTA.
// 64 CTAs x 512 threads. CTA c owns batches b0=2c, b1=2c+1.
// Thread (j = tid&255, half = tid>>8): k-range [half*128, half*128+128).
//   W slice: NREG=20 float4 in regs (80 regs), NTAIL=12 float4 in SMEM.
//   Each W value (reg or SMEM, loaded once) feeds BOTH batches' FMA chains:
//   W crossbar traffic per batch halves, and the two independent dot chains
//   overlap each other's LDS latency.
// Exchange: (j,0) sends its batch1 partial -> psB[j]; (j,1) sends its batch0
// partial -> psA[j]. After bar, half h finalizes batch h (xp + tanh + publish)
// -- both halves busy. 2 barriers/step, double-buffered h per batch.
// ---------------------------------------------------------------------------
#define NREG 20
#define NTAIL 12

__global__ void __launch_bounds__(512, 1)
rnn_scan(const float* __restrict__ W_hh,
         const float* __restrict__ W_fc,
         const float* __restrict__ b_fc,
         float* __restrict__ out) {
    extern __shared__ float sm[];
    float4* wt4 = (float4*)sm;                        // [2*NTAIL][256] f4 = 96 KB
    float*  h0A = sm + 2 * NTAIL * 256 * 4;           // batch0 h buffers
    float*  h0B = h0A + HH;
    float*  h1A = h0B + HH;                           // batch1 h buffers
    float*  h1B = h1A + HH;
    float*  psA = h1B + HH;                           // batch0 partial (from half1)
    float*  psB = psA + HH;                           // batch1 partial (from half0)
    float*  red0 = psB + HH;                          // 8
    float*  red1 = red0 + 8;                          // 8

    const int tid  = threadIdx.x;
    const int j    = tid & 255;
    const int half = tid >> 8;
    const int b0   = 2 * blockIdx.x;
    const int b1   = b0 + 1;

    const float4* W4 = (const float4*)W_hh;           // row j = W4[j*64 .. +63]
    const int wbase = j * 64 + half * 32;

    float4 wreg[NREG];
#pragma unroll
    for (int q = 0; q < NREG; q++) wreg[q] = W4[wbase + q];

#pragma unroll
    for (int q = 0; q < NTAIL; q++)
        wt4[(half * NTAIL + q) * 256 + j] = W4[wbase + NREG + q];

    if (tid < HH) { h0A[tid] = 0.0f; h1A[tid] = 0.0f; }
    __syncthreads();

    const float* xp = (half == 0)
        ? g_xp + (size_t)b0 * TT * HH + j
        : g_xp + (size_t)b1 * TT * HH + j;

    const float4* wt = wt4 + half * NTAIL * 256 + j;  // wt[q*256]

    float* h0cur = h0A; float* h0nxt = h0B;
    float* h1cur = h1A; float* h1nxt = h1B;
    float hn = 0.0f;                                  // half h's final h for batch h

    for (int t = 0; t < TT; t++) {
        const float xpv = xp[(size_t)t * HH];         // early issue, L2-hit

        const float4* h0p = (const float4*)(h0cur + half * 128);
        const float4* h1p = (const float4*)(h1cur + half * 128);

        float2 a0 = make_float2(0.0f, 0.0f), a1 = a0;   // batch0 chains
        float2 c0 = a0, c1 = a0;                        // batch1 chains

        // SMEM W-tail first (latency overlaps the register-W FMA stream)
#pragma unroll
        for (int q = 0; q < NTAIL; q++) {
            float4 w4 = wt[q * 256];
            float4 f0 = h0p[NREG + q];
            float4 f1 = h1p[NREG + q];
            a0 = ffma2(make_float2(f0.x, f0.y), make_float2(w4.x, w4.y), a0);
            a1 = ffma2(make_float2(f0.z, f0.w), make_float2(w4.z, w4.w), a1);
            c0 = ffma2(make_float2(f1.x, f1.y), make_float2(w4.x, w4.y), c0);
            c1 = ffma2(make_float2(f1.z, f1.w), make_float2(w4.z, w4.w), c1);
        }
#pragma unroll
        for (int q = 0; q < NREG; q++) {
            float4 w4 = wreg[q];
            float4 f0 = h0p[q];
            float4 f1 = h1p[q];
            a0 = ffma2(make_float2(f0.x, f0.y), make_float2(w4.x, w4.y), a0);
            a1 = ffma2(make_float2(f0.z, f0.w), make_float2(w4.z, w4.w), a1);
            c0 = ffma2(make_float2(f1.x, f1.y), make_float2(w4.x, w4.y), c0);
            c1 = ffma2(make_float2(f1.z, f1.w), make_float2(w4.z, w4.w), c1);
        }

        const float dot0 = (a0.x + a0.y) + (a1.x + a1.y);   // batch0 half-dot
        const float dot1 = (c0.x + c0.y) + (c1.x + c1.y);   // batch1 half-dot

        // cross-ship the partial for the batch the OTHER half finalizes
        if (half == 0) psB[j] = dot1; else psA[j] = dot0;
        __syncthreads();                 // partials visible; hcur reads done

        if (half == 0) {
            hn = tanhf(xpv + dot0 + psA[j]);
            h0nxt[j] = hn;
        } else {
            hn = tanhf(xpv + dot1 + psB[j]);
            h1nxt[j] = hn;
        }
        __syncthreads();                 // new h visible

        float* tmp;
        tmp = h0cur; h0cur = h0nxt; h0nxt = tmp;
        tmp = h1cur; h1cur = h1nxt; h1nxt = tmp;
    }

    // Phase 3: out[b] = sigmoid(h . W_fc + b_fc), per half/batch
    float v = hn * W_fc[j];
#pragma unroll
    for (int o = 16; o > 0; o >>= 1) v += __shfl_down_sync(0xffffffffu, v, o);
    if ((j & 31) == 0) {
        if (half == 0) red0[j >> 5] = v; else red1[j >> 5] = v;
    }
    __syncthreads();
    if (tid == 0) {
        float s = b_fc[0];
#pragma unroll
        for (int w = 0; w < 8; w++) s += red0[w];
        out[b0] = 1.0f / (1.0f + expf(-s));
    }
    if (tid == 256) {
        float s = b_fc[0];
#pragma unroll
        for (int w = 0; w < 8; w++) s += red1[w];
        out[b1] = 1.0f / (1.0f + expf(-s));
    }
}

// ---------------------------------------------------------------------------

extern "C" void kernel_launch(void* const* d_in, const int* in_sizes, int n_in,
                              void* d_out, int out_size) {
    const float* x    = (const float*)d_in[0];
    const float* W_ih = (const float*)d_in[1];
    const float* W_hh = (const float*)d_in[2];
    const float* b_ih = (const float*)d_in[3];
    const float* b_hh = (const float*)d_in[4];
    const float* W_fc = (const float*)d_in[5];
    const float* b_fc = (const float*)d_in[6];
    float* out = (float*)d_out;

    const int smem_b = (2 * NTAIL * 256 * 4 + 6 * HH + 16) * (int)sizeof(float); // ~104.3 KB
    cudaFuncSetAttribute(rnn_scan, cudaFuncAttributeMaxDynamicSharedMemorySize, smem_b);

    rnn_xproj<<<128, 256>>>(x, W_ih, b_ih, b_hh);
    rnn_scan<<<BB / 2, 512, smem_b>>>(W_hh, W_fc, b_fc, out);
}

// round 7
// speedup vs baseline: 1.0754x; 1.0754x over previous
#include <cuda_runtime.h>
#include <cstring>

#define BB 128
#define TT 512
#define II 128
#define HH 256

__device__ float g_xp[(size_t)BB * TT * HH];   // [B][T][H] fp32 scratch (fits L2)

// Packed fp32x2 FMA (sm_103a).
__device__ __forceinline__ float2 ffma2(float2 a, float2 b, float2 c) {
    unsigned long long ua, ub, uc, ud;
    memcpy(&ua, &a, 8); memcpy(&ub, &b, 8); memcpy(&uc, &c, 8);
    asm("fma.rn.f32x2 %0, %1, %2, %3;" : "=l"(ud) : "l"(ua), "l"(ub), "l"(uc));
    float2 d; memcpy(&d, &ud, 8); return d;
}

// Safe fast tanh: e = exp(-2|x|) in (0,1] -> no overflow; rel err ~1e-6.
__device__ __forceinline__ float fast_tanh(float x) {
    float e = __expf(-2.0f * fabsf(x));
    float r = __fdividef(1.0f - e, 1.0f + e);
    return copysignf(r, x);
}

// ---------------------------------------------------------------------------
// Phase 1: xp[r,h] = x[r,:] . W_ih[h,:] + (b_ih[h] + b_hh[h])
// 128 CTAs x 256 threads; W_ih row per thread in regs; x double-buffered.
// ---------------------------------------------------------------------------
__global__ void __launch_bounds__(256, 1)
rnn_xproj(const float* __restrict__ x,
          const float* __restrict__ W_ih,
          const float* __restrict__ b_ih,
          const float* __restrict__ b_hh) {
    __shared__ float xs[2][8 * II];

    const int h = threadIdx.x;

    const float4* Wi4 = (const float4*)W_ih;
    float4 wreg[32];
#pragma unroll
    for (int q = 0; q < 32; q++) wreg[q] = Wi4[h * 32 + q];

    const float bias = b_ih[h] + b_hh[h];
    const size_t base_row = (size_t)blockIdx.x * 512;

    ((float4*)xs[0])[h] = ((const float4*)(x + base_row * II))[h];
    __syncthreads();

    for (int tile = 0; tile < 64; tile++) {
        const int cur = tile & 1;
        if (tile < 63) {
            ((float4*)xs[cur ^ 1])[h] =
                ((const float4*)(x + (base_row + (size_t)(tile + 1) * 8) * II))[h];
        }

        const size_t r0 = base_row + (size_t)tile * 8;
#pragma unroll
        for (int r = 0; r < 8; r += 2) {
            const float4* x0 = (const float4*)(xs[cur] + r * II);
            const float4* x1 = (const float4*)(xs[cur] + (r + 1) * II);
            float2 a0 = make_float2(bias, 0.0f), a1 = make_float2(0.0f, 0.0f);
            float2 c0 = make_float2(bias, 0.0f), c1 = make_float2(0.0f, 0.0f);
#pragma unroll
            for (int q = 0; q < 32; q++) {
                float4 xv = x0[q], yv = x1[q];
                float2 wlo = make_float2(wreg[q].x, wreg[q].y);
                float2 whi = make_float2(wreg[q].z, wreg[q].w);
                a0 = ffma2(make_float2(xv.x, xv.y), wlo, a0);
                a1 = ffma2(make_float2(xv.z, xv.w), whi, a1);
                c0 = ffma2(make_float2(yv.x, yv.y), wlo, c0);
                c1 = ffma2(make_float2(yv.z, yv.w), whi, c1);
            }
            g_xp[(r0 + r) * HH + h]     = (a0.x + a0.y) + (a1.x + a1.y);
            g_xp[(r0 + r + 1) * HH + h] = (c0.x + c0.y) + (c1.x + c1.y);
        }
        __syncthreads();
    }
}

// ---------------------------------------------------------------------------
// Phase 2 + 3: recurrent scan. 128 CTAs x 512 threads (16 warps).
// WARP-PAIR LAYOUT: warp w, lane l -> feature j = w*16 + (l>>1),
// k-half = l&1 (k range [khalf*128, khalf*128+128)).
//   - W slice: NREG=20 float4 in regs, NTAIL=12 float4 in SMEM [seg][j].
//   - h in SMEM, halves at float-offsets 0 and 132 (4-float pad keeps the
//     pair's two broadcast addresses on disjoint banks -> 1 wf per h-load).
//   - partial exchange: shfl.bfly xor 1 (in-register; no ps[] SMEM, no bar).
//   - ONE __syncthreads per step (publish h to the other buffer, swap).
//   - fast_tanh instead of tanhf.
// ---------------------------------------------------------------------------
#define NREG 20
#define NTAIL 12
#define HPAD 132          // float offset of k-half 1 within an h buffer
#define HBUF 264          // floats per h buffer (132*2)

__global__ void __launch_bounds__(512, 1)
rnn_scan(const float* __restrict__ W_hh,
         const float* __restrict__ W_fc,
         const float* __restrict__ b_fc,
         float* __restrict__ out) {
    extern __shared__ float sm[];
    float4* wt4 = (float4*)sm;                  // [2*NTAIL][256] f4 = 96 KB
    float*  hA  = sm + 2 * NTAIL * 256 * 4;     // HBUF floats
    float*  hB  = hA + HBUF;                    // HBUF floats
    float*  red = hB + HBUF;                    // 8 floats

    const int tid   = threadIdx.x;
    const int lane  = tid & 31;
    const int wid   = tid >> 5;
    const int j     = (wid << 4) | (lane >> 1); // 0..255
    const int khalf = lane & 1;
    const int b     = blockIdx.x;

    const float4* W4 = (const float4*)W_hh;     // row j = W4[j*64 .. +63]
    const int wbase = j * 64 + khalf * 32;

    float4 wreg[NREG];
#pragma unroll
    for (int q = 0; q < NREG; q++) wreg[q] = W4[wbase + q];

#pragma unroll
    for (int q = 0; q < NTAIL; q++)
        wt4[(khalf * NTAIL + q) * 256 + j] = W4[wbase + NREG + q];

    for (int idx = tid; idx < 2 * HBUF; idx += 512) {
        if (idx < HBUF) hA[idx] = 0.0f; else hB[idx - HBUF] = 0.0f;
    }
    __syncthreads();

    const float* xp = g_xp + (size_t)b * TT * HH + j;
    const float4* wt = wt4 + khalf * NTAIL * 256 + j;   // wt[q*256]
    const int jsto = j + ((j >= 128) ? 4 : 0);          // padded store index

    float* hcur = hA;
    float* hnxt = hB;

    for (int t = 0; t < TT; t++) {
        const float xpv = xp[(size_t)t * HH];           // early issue, L2-hit

        const float4* h4p = (const float4*)(hcur + khalf * HPAD);
        float2 a0 = make_float2(0.0f, 0.0f), a1 = a0, a2 = a0, a3 = a0;

        // SMEM W-tail first: LDS latency overlaps the register-W FMA stream
#pragma unroll
        for (int q = 0; q < NTAIL; q++) {
            float4 h4 = h4p[NREG + q];
            float4 w4 = wt[q * 256];
            if (q & 1) {
                a2 = ffma2(make_float2(h4.x, h4.y), make_float2(w4.x, w4.y), a2);
                a3 = ffma2(make_float2(h4.z, h4.w), make_float2(w4.z, w4.w), a3);
            } else {
                a0 = ffma2(make_float2(h4.x, h4.y), make_float2(w4.x, w4.y), a0);
                a1 = ffma2(make_float2(h4.z, h4.w), make_float2(w4.z, w4.w), a1);
            }
        }
#pragma unroll
        for (int q = 0; q < NREG; q++) {
            float4 h4 = h4p[q];
            if (q & 1) {
                a2 = ffma2(make_float2(h4.x, h4.y), make_float2(wreg[q].x, wreg[q].y), a2);
                a3 = ffma2(make_float2(h4.z, h4.w), make_float2(wreg[q].z, wreg[q].w), a3);
            } else {
                a0 = ffma2(make_float2(h4.x, h4.y), make_float2(wreg[q].x, wreg[q].y), a0);
                a1 = ffma2(make_float2(h4.z, h4.w), make_float2(wreg[q].z, wreg[q].w), a1);
            }
        }

        const float mydot = ((a0.x + a0.y) + (a1.x + a1.y)) +
                            ((a2.x + a2.y) + (a3.x + a3.y));

        // in-warp exchange of the two half-dots (no SMEM, no barrier)
        const float other = __shfl_xor_sync(0xffffffffu, mydot, 1);
        const float d0 = (khalf == 0) ? mydot : other;   // k-lo partial
        const float d1 = (khalf == 0) ? other : mydot;   // k-hi partial
        const float hn = fast_tanh(xpv + d0 + d1);       // identical in both lanes

        if (khalf == 0) hnxt[jsto] = hn;                 // even lanes publish
        __syncthreads();                                 // new h visible

        float* tmp = hcur; hcur = hnxt; hnxt = tmp;
    }

    // Phase 3: out[b] = sigmoid(h . W_fc + b_fc)  (first 256 threads)
    if (tid < HH) {
        const float hv = hcur[tid + ((tid >= 128) ? 4 : 0)];
        float v = hv * W_fc[tid];
#pragma unroll
        for (int o = 16; o > 0; o >>= 1) v += __shfl_down_sync(0xffffffffu, v, o);
        if ((tid & 31) == 0) red[tid >> 5] = v;
    }
    __syncthreads();
    if (tid == 0) {
        float s = b_fc[0];
#pragma unroll
        for (int w = 0; w < 8; w++) s += red[w];
        out[b] = 1.0f / (1.0f + expf(-s));
    }
}

// ---------------------------------------------------------------------------

extern "C" void kernel_launch(void* const* d_in, const int* in_sizes, int n_in,
                              void* d_out, int out_size) {
    const float* x    = (const float*)d_in[0];
    const float* W_ih = (const float*)d_in[1];
    const float* W_hh = (const float*)d_in[2];
    const float* b_ih = (const float*)d_in[3];
    const float* b_hh = (const float*)d_in[4];
    const float* W_fc = (const float*)d_in[5];
    const float* b_fc = (const float*)d_in[6];
    float* out = (float*)d_out;

    const int smem_b = (2 * NTAIL * 256 * 4 + 2 * HBUF + 8) * (int)sizeof(float); // ~98.4 KB
    cudaFuncSetAttribute(rnn_scan, cudaFuncAttributeMaxDynamicSharedMemorySize, smem_b);

    rnn_xproj<<<128, 256>>>(x, W_ih, b_ih, b_hh);
    rnn_scan<<<BB, 512, smem_b>>>(W_hh, W_fc, b_fc, out);
}

// round 8
// speedup vs baseline: 1.4571x; 1.3549x over previous
#include <cuda_runtime.h>
#include <cstring>

#define BB 128
#define TT 512
#define II 128
#define HH 256

__device__ float g_xp[(size_t)BB * TT * HH];   // [B][T][H] fp32 scratch (fits L2)

// Packed fp32x2 FMA (sm_103a).
__device__ __forceinline__ float2 ffma2(float2 a, float2 b, float2 c) {
    unsigned long long ua, ub, uc, ud;
    memcpy(&ua, &a, 8); memcpy(&ub, &b, 8); memcpy(&uc, &c, 8);
    asm("fma.rn.f32x2 %0, %1, %2, %3;" : "=l"(ud) : "l"(ua), "l"(ub), "l"(uc));
    float2 d; memcpy(&d, &ud, 8); return d;
}

// Safe fast tanh: e = exp(-2|x|) in (0,1] -> no overflow; rel err ~1e-6.
// (Validated R7: end-to-end rel_err 6.4e-8.)
__device__ __forceinline__ float fast_tanh(float x) {
    float e = __expf(-2.0f * fabsf(x));
    float r = __fdividef(1.0f - e, 1.0f + e);
    return copysignf(r, x);
}

// ---------------------------------------------------------------------------
// Phase 1: xp[r,h] = x[r,:] . W_ih[h,:] + (b_ih[h] + b_hh[h])
// 128 CTAs x 256 threads; W_ih row per thread in regs; x double-buffered.
// ---------------------------------------------------------------------------
__global__ void __launch_bounds__(256, 1)
rnn_xproj(const float* __restrict__ x,
          const float* __restrict__ W_ih,
          const float* __restrict__ b_ih,
          const float* __restrict__ b_hh) {
    __shared__ float xs[2][8 * II];

    const int h = threadIdx.x;

    const float4* Wi4 = (const float4*)W_ih;
    float4 wreg[32];
#pragma unroll
    for (int q = 0; q < 32; q++) wreg[q] = Wi4[h * 32 + q];

    const float bias = b_ih[h] + b_hh[h];
    const size_t base_row = (size_t)blockIdx.x * 512;

    ((float4*)xs[0])[h] = ((const float4*)(x + base_row * II))[h];
    __syncthreads();

    for (int tile = 0; tile < 64; tile++) {
        const int cur = tile & 1;
        if (tile < 63) {
            ((float4*)xs[cur ^ 1])[h] =
                ((const float4*)(x + (base_row + (size_t)(tile + 1) * 8) * II))[h];
        }

        const size_t r0 = base_row + (size_t)tile * 8;
#pragma unroll
        for (int r = 0; r < 8; r += 2) {
            const float4* x0 = (const float4*)(xs[cur] + r * II);
            const float4* x1 = (const float4*)(xs[cur] + (r + 1) * II);
            float2 a0 = make_float2(bias, 0.0f), a1 = make_float2(0.0f, 0.0f);
            float2 c0 = make_float2(bias, 0.0f), c1 = make_float2(0.0f, 0.0f);
#pragma unroll
            for (int q = 0; q < 32; q++) {
                float4 xv = x0[q], yv = x1[q];
                float2 wlo = make_float2(wreg[q].x, wreg[q].y);
                float2 whi = make_float2(wreg[q].z, wreg[q].w);
                a0 = ffma2(make_float2(xv.x, xv.y), wlo, a0);
                a1 = ffma2(make_float2(xv.z, xv.w), whi, a1);
                c0 = ffma2(make_float2(yv.x, yv.y), wlo, c0);
                c1 = ffma2(make_float2(yv.z, yv.w), whi, c1);
            }
            g_xp[(r0 + r) * HH + h]     = (a0.x + a0.y) + (a1.x + a1.y);
            g_xp[(r0 + r + 1) * HH + h] = (c0.x + c0.y) + (c1.x + c1.y);
        }
        __syncthreads();
    }
}

// ---------------------------------------------------------------------------
// Phase 2 + 3: recurrent scan. 128 CTAs x 512 threads (16 warps).
// PARITY-PAIR LAYOUT: warp w, lane l -> feature j = w*16 + (l>>1),
// parity p = l&1. Thread (j,p) takes W/h float4 indices {2*qq + p}, qq=0..31
// (interleaved over the FULL k=256). Consequences:
//   - every h LDS.128 presents addresses X and X+16 (same 128B segment)
//     -> 1 wavefront (R7's k-half split hit 2 segments -> 2 wf: the bug).
//   - partial exchange = shfl.xor(1) in-warp; ONE __syncthreads per step.
//   - W: qq<NREG in regs; tail in SMEM [qq][j*2+p] (warp reads 512B consec).
// ---------------------------------------------------------------------------
#define NREG 22
#define NTAIL 10

__global__ void __launch_bounds__(512, 1)
rnn_scan(const float* __restrict__ W_hh,
         const float* __restrict__ W_fc,
         const float* __restrict__ b_fc,
         float* __restrict__ out) {
    extern __shared__ float sm[];
    float4* wt4 = (float4*)sm;                  // [NTAIL][512] float4 = 80 KB
    float*  hA  = sm + NTAIL * 512 * 4;         // 256 floats
    float*  hB  = hA + HH;                      // 256 floats
    float*  red = hB + HH;                      // 8 floats

    const int tid  = threadIdx.x;
    const int lane = tid & 31;
    const int w    = tid >> 5;
    const int j    = (w << 4) | (lane >> 1);    // 0..255
    const int p    = lane & 1;
    const int b    = blockIdx.x;

    const float4* W4 = (const float4*)W_hh;     // row j = W4[j*64 .. +63]

    // W float4 indices 2*qq+p, qq = 0..31. First NREG in regs, rest in SMEM.
    float4 wreg[NREG];
#pragma unroll
    for (int qq = 0; qq < NREG; qq++) wreg[qq] = W4[j * 64 + 2 * qq + p];

#pragma unroll
    for (int qq = 0; qq < NTAIL; qq++)
        wt4[qq * 512 + j * 2 + p] = W4[j * 64 + 2 * (NREG + qq) + p];

    if (tid < HH) { hA[tid] = 0.0f; hB[tid] = 0.0f; }
    __syncthreads();

    const float*  xp  = g_xp + (size_t)b * TT * HH + j;
    const float4* wtp = wt4 + j * 2 + p;        // wtp[qq*512]

    float* hcur = hA;
    float* hnxt = hB;

    for (int t = 0; t < TT; t++) {
        const float xpv = xp[(size_t)t * HH];   // early issue, L2-hit

        const float4* hs4 = (const float4*)hcur;
        float2 a0 = make_float2(0.0f, 0.0f), a1 = a0, a2 = a0, a3 = a0;

        // SMEM W-tail first: LDS latency overlaps the register-W FMA stream
#pragma unroll
        for (int qq = 0; qq < NTAIL; qq++) {
            float4 h4 = hs4[2 * (NREG + qq) + p];
            float4 w4 = wtp[qq * 512];
            if (qq & 1) {
                a2 = ffma2(make_float2(h4.x, h4.y), make_float2(w4.x, w4.y), a2);
                a3 = ffma2(make_float2(h4.z, h4.w), make_float2(w4.z, w4.w), a3);
            } else {
                a0 = ffma2(make_float2(h4.x, h4.y), make_float2(w4.x, w4.y), a0);
                a1 = ffma2(make_float2(h4.z, h4.w), make_float2(w4.z, w4.w), a1);
            }
        }
#pragma unroll
        for (int qq = 0; qq < NREG; qq++) {
            float4 h4 = hs4[2 * qq + p];
            if (qq & 1) {
                a2 = ffma2(make_float2(h4.x, h4.y), make_float2(wreg[qq].x, wreg[qq].y), a2);
                a3 = ffma2(make_float2(h4.z, h4.w), make_float2(wreg[qq].z, wreg[qq].w), a3);
            } else {
                a0 = ffma2(make_float2(h4.x, h4.y), make_float2(wreg[qq].x, wreg[qq].y), a0);
                a1 = ffma2(make_float2(h4.z, h4.w), make_float2(wreg[qq].z, wreg[qq].w), a1);
            }
        }

        const float mydot = ((a0.x + a0.y) + (a1.x + a1.y)) +
                            ((a2.x + a2.y) + (a3.x + a3.y));

        // in-warp exchange of the two parity partials (no SMEM, no extra bar)
        const float other = __shfl_xor_sync(0xffffffffu, mydot, 1);
        const float hn = fast_tanh(xpv + mydot + other);  // identical in pair

        if (p == 0) hnxt[j] = hn;               // even lanes publish (16 consec/warp)
        __syncthreads();                        // single barrier: h published

        float* tmp = hcur; hcur = hnxt; hnxt = tmp;
    }

    // Phase 3: out[b] = sigmoid(h . W_fc + b_fc)  (first 256 threads)
    if (tid < HH) {
        float v = hcur[tid] * W_fc[tid];
#pragma unroll
        for (int o = 16; o > 0; o >>= 1) v += __shfl_down_sync(0xffffffffu, v, o);
        if ((tid & 31) == 0) red[tid >> 5] = v;
    }
    __syncthreads();
    if (tid == 0) {
        float s = b_fc[0];
#pragma unroll
        for (int w2 = 0; w2 < 8; w2++) s += red[w2];
        out[b] = 1.0f / (1.0f + expf(-s));
    }
}

// ---------------------------------------------------------------------------

extern "C" void kernel_launch(void* const* d_in, const int* in_sizes, int n_in,
                              void* d_out, int out_size) {
    const float* x    = (const float*)d_in[0];
    const float* W_ih = (const float*)d_in[1];
    const float* W_hh = (const float*)d_in[2];
    const float* b_ih = (const float*)d_in[3];
    const float* b_hh = (const float*)d_in[4];
    const float* W_fc = (const float*)d_in[5];
    const float* b_fc = (const float*)d_in[6];
    float* out = (float*)d_out;

    const int smem_b = (NTAIL * 512 * 4 + 2 * HH + 8) * (int)sizeof(float); // ~84 KB
    cudaFuncSetAttribute(rnn_scan, cudaFuncAttributeMaxDynamicSharedMemorySize, smem_b);

    rnn_xproj<<<128, 256>>>(x, W_ih, b_ih, b_hh);
    rnn_scan<<<BB, 512, smem_b>>>(W_hh, W_fc, b_fc, out);
}